// round 13
// baseline (speedup 1.0000x reference)
#include <cuda_runtime.h>
#include <cstdint>

// ==================== problem constants ====================
static constexpr int IN_DIM  = 64;
static constexpr int HID     = 128;
static constexpr int OUT_DIM = 64;

static constexpr int THREADS      = 128;   // 4 warps
static constexpr int MI           = 2;     // 2 x 16 = 32 rows per CTA
static constexpr int ROWS_PER_CTA = 16 * MI;
static constexpr int KS           = HID / 16;   // 8 k-steps of 16
// z exchange (fp16 A-frags), double buffered: (MI*KS) tiles x 32 slots x 16B
static constexpr int BUF_BYTES  = (MI * KS) * 32 * 16;        // 8 KB
static constexpr int OFF_INJ    = 2 * BUF_BYTES;              // 16 KB in
static constexpr int SMEM_TOTAL = OFF_INJ + THREADS * 128;    // 32 KB

// ==================== small helpers ====================
__device__ __forceinline__ uint32_t pack_h2(float lo, float hi) {
    uint32_t d;
    asm("cvt.rn.f16x2.f32 %0, %1, %2;" : "=r"(d) : "f"(hi), "f"(lo));
    return d;
}
__device__ __forceinline__ uint32_t pack_h2_relu(float lo, float hi) {
    uint32_t d;
    asm("cvt.rn.relu.f16x2.f32 %0, %1, %2;" : "=r"(d) : "f"(hi), "f"(lo));
    return d;
}

// D(f32) += A(f16 m16n8k16) * B(f16)
__device__ __forceinline__ void mma_f16(float* d, const uint32_t* a, const uint32_t* b) {
    asm volatile(
        "mma.sync.aligned.m16n8k16.row.col.f32.f16.f16.f32 "
        "{%0,%1,%2,%3},{%4,%5,%6,%7},{%8,%9},{%0,%1,%2,%3};"
        : "+f"(d[0]), "+f"(d[1]), "+f"(d[2]), "+f"(d[3])
        : "r"(a[0]), "r"(a[1]), "r"(a[2]), "r"(a[3]), "r"(b[0]), "r"(b[1]));
}

// slot swizzle (involution; conflict-free LDS.128 loads & STS.64 stores)
__device__ __forceinline__ int swz(int l) { return l ^ (((l >> 3) & 1) << 2); }

// ==================== kernel ====================
__global__ void __launch_bounds__(THREADS, 4)
deq_mma_kernel(const float* __restrict__ x,
               const float* __restrict__ Wz,
               const float* __restrict__ Ux,
               const float* __restrict__ b,
               const float* __restrict__ Wd,
               const float* __restrict__ bd,
               const int*   __restrict__ nitp,
               float* __restrict__ out,
               int rows) {
    extern __shared__ char sm[];      // 2 x 8KB z bufs + 16KB inj segments
    const int tid  = threadIdx.x;
    const int w    = tid >> 5;        // warp owns col slice [32w, 32w+32)
    const int lane = tid & 31;
    const int g    = lane >> 2;       // row-in-8 (groupID)
    const int c    = lane & 3;        // threadID-in-group
    const int n_iters = *nitp;

    const long rowbase = (long)blockIdx.x * ROWS_PER_CTA;
    const uint32_t lanerd = (uint32_t)swz(lane) << 4;   // own 16B slot offset
    char* injseg = sm + OFF_INJ + (uint32_t)tid * 128u; // thread-private inj

    // B-fragment register file (fp16x2 pairs). Wz: [s:8][ni:4] = 64 regs.
    // Reused: Ux [s:4][ni:4], Wd [s:8][ni:2].
    uint32_t B[32][2];

    // ---------------- load Ux B-frags (K=64 -> 4 k-steps) ----------------
#pragma unroll
    for (int s = 0; s < 4; s++)
#pragma unroll
        for (int ni = 0; ni < 4; ni++) {
            const float* src = Ux + (32 * w + 8 * ni + g) * IN_DIM + 16 * s + 2 * c;
            B[s * 4 + ni][0] = pack_h2(__ldg(src),     __ldg(src + 1));
            B[s * 4 + ni][1] = pack_h2(__ldg(src + 8), __ldg(src + 9));
        }

    // ---------------- inj = x @ Ux^T (in regs, then spilled to private smem) ----------------
    {
        float inj[MI][4][4];
#pragma unroll
        for (int mi = 0; mi < MI; mi++)
#pragma unroll
            for (int ni = 0; ni < 4; ni++)
#pragma unroll
                for (int r = 0; r < 4; r++) inj[mi][ni][r] = 0.0f;

#pragma unroll
        for (int s = 0; s < 4; s++) {
#pragma unroll
            for (int mi = 0; mi < MI; mi++) {
                uint32_t A[4];
                long r0 = rowbase + 16 * mi + g;
                long r1 = r0 + 8;
                const float* x0 = x + r0 * IN_DIM + 16 * s + 2 * c;
                const float* x1 = x + r1 * IN_DIM + 16 * s + 2 * c;
                float2 p0 = (r0 < rows) ? *reinterpret_cast<const float2*>(x0)     : make_float2(0.f, 0.f);
                float2 p1 = (r1 < rows) ? *reinterpret_cast<const float2*>(x1)     : make_float2(0.f, 0.f);
                float2 p2 = (r0 < rows) ? *reinterpret_cast<const float2*>(x0 + 8) : make_float2(0.f, 0.f);
                float2 p3 = (r1 < rows) ? *reinterpret_cast<const float2*>(x1 + 8) : make_float2(0.f, 0.f);
                A[0] = pack_h2(p0.x, p0.y);
                A[1] = pack_h2(p1.x, p1.y);
                A[2] = pack_h2(p2.x, p2.y);
                A[3] = pack_h2(p3.x, p3.y);
#pragma unroll
                for (int ni = 0; ni < 4; ni++)
                    mma_f16(inj[mi][ni], A, B[s * 4 + ni]);
            }
        }

        // add bias; save inj (f32, private smem); scatter z1 = relu(inj) to buf 0
#pragma unroll
        for (int ni = 0; ni < 4; ni++) {
            float b0v = __ldg(b + 32 * w + 8 * ni + 2 * c);
            float b1v = __ldg(b + 32 * w + 8 * ni + 2 * c + 1);
#pragma unroll
            for (int mi = 0; mi < MI; mi++) {
                float4 v;
                v.x = inj[mi][ni][0] + b0v;
                v.y = inj[mi][ni][1] + b1v;
                v.z = inj[mi][ni][2] + b0v;
                v.w = inj[mi][ni][3] + b1v;
                *reinterpret_cast<float4*>(injseg + (uint32_t)(mi * 64 + ni * 16)) = v;

                uint2 zv;
                zv.x = pack_h2_relu(v.x, v.y);   // rows g, g+8, cols 2c(+1)
                zv.y = pack_h2_relu(v.z, v.w);   // cols +8
                uint32_t tile = (uint32_t)(mi * KS + 2 * w + (ni >> 1));
                uint32_t addr = tile * 512u + lanerd + ((uint32_t)(ni & 1) << 3);
                *reinterpret_cast<uint2*>(sm + addr) = zv;
            }
        }
    }

    // ---------------- load Wz B-frags (once; K=128 -> 8 k-steps) ----------------
#pragma unroll
    for (int s = 0; s < KS; s++)
#pragma unroll
        for (int ni = 0; ni < 4; ni++) {
            const float* src = Wz + (32 * w + 8 * ni + g) * HID + 16 * s + 2 * c;
            B[s * 4 + ni][0] = pack_h2(__ldg(src),     __ldg(src + 1));
            B[s * 4 + ni][1] = pack_h2(__ldg(src + 8), __ldg(src + 9));
        }
    __syncthreads();   // z1 scatter visible to all warps

    // ---------------- fixed-point loop: mi-split pipeline, one sync/iter ----------------
    char* rd = sm;
    char* wr = sm + BUF_BYTES;
    for (int it = 1; it < n_iters; it++) {
#pragma unroll
        for (int mi = 0; mi < MI; mi++) {
            // acc starts at inj (read from thread-private smem; exact f32)
            float acc[4][4];
#pragma unroll
            for (int ni = 0; ni < 4; ni++) {
                float4 v = *reinterpret_cast<const float4*>(injseg + (uint32_t)(mi * 64 + ni * 16));
                acc[ni][0] = v.x; acc[ni][1] = v.y; acc[ni][2] = v.z; acc[ni][3] = v.w;
            }

            const char* rdm = rd + (uint32_t)(mi * KS * 512);
#pragma unroll
            for (int s = 0; s < KS; s++) {
                uint4 a = *reinterpret_cast<const uint4*>(rdm + (uint32_t)(s * 512) + lanerd);
                uint32_t A[4] = {a.x, a.y, a.z, a.w};
#pragma unroll
                for (int ni = 0; ni < 4; ni++)
                    mma_f16(acc[ni], A, B[s * 4 + ni]);
            }

            // epilogue for this mi (stores overlap next mi's / other CTAs' MMAs)
            char* wrm = wr + (uint32_t)(mi * KS * 512);
#pragma unroll
            for (int ni = 0; ni < 4; ni++) {
                uint2 v;
                v.x = pack_h2_relu(acc[ni][0], acc[ni][1]);
                v.y = pack_h2_relu(acc[ni][2], acc[ni][3]);
                uint32_t tile = (uint32_t)(2 * w + (ni >> 1));
                uint32_t addr = tile * 512u + lanerd + ((uint32_t)(ni & 1) << 3);
                *reinterpret_cast<uint2*>(wrm + addr) = v;
            }
        }
        __syncthreads();
        char* t = rd; rd = wr; wr = t;
    }

    // ---------------- decoder: out = z @ Wd^T + bd ----------------
    // warp w computes cols [16w, 16w+16): ni 0..1
#pragma unroll
    for (int s = 0; s < KS; s++)
#pragma unroll
        for (int ni = 0; ni < 2; ni++) {
            const float* src = Wd + (16 * w + 8 * ni + g) * HID + 16 * s + 2 * c;
            B[s * 2 + ni][0] = pack_h2(__ldg(src),     __ldg(src + 1));
            B[s * 2 + ni][1] = pack_h2(__ldg(src + 8), __ldg(src + 9));
        }

#pragma unroll
    for (int mi = 0; mi < MI; mi++) {
        float acc2[2][4];
#pragma unroll
        for (int ni = 0; ni < 2; ni++)
#pragma unroll
            for (int r = 0; r < 4; r++) acc2[ni][r] = 0.0f;

        const char* rdm = rd + (uint32_t)(mi * KS * 512);
#pragma unroll
        for (int s = 0; s < KS; s++) {
            uint4 a = *reinterpret_cast<const uint4*>(rdm + (uint32_t)(s * 512) + lanerd);
            uint32_t A[4] = {a.x, a.y, a.z, a.w};
#pragma unroll
            for (int ni = 0; ni < 2; ni++)
                mma_f16(acc2[ni], A, B[s * 2 + ni]);
        }

        long r0 = rowbase + 16 * mi + g;
        long r1 = r0 + 8;
#pragma unroll
        for (int ni = 0; ni < 2; ni++) {
            int colb = 16 * w + 8 * ni + 2 * c;
            float bd0 = __ldg(bd + colb);
            float bd1 = __ldg(bd + colb + 1);
            if (r0 < rows) {
                float2 v0 = make_float2(acc2[ni][0] + bd0, acc2[ni][1] + bd1);
                *reinterpret_cast<float2*>(out + r0 * OUT_DIM + colb) = v0;
            }
            if (r1 < rows) {
                float2 v1 = make_float2(acc2[ni][2] + bd0, acc2[ni][3] + bd1);
                *reinterpret_cast<float2*>(out + r1 * OUT_DIM + colb) = v1;
            }
        }
    }
}

// ==================== launch ====================
extern "C" void kernel_launch(void* const* d_in, const int* in_sizes, int n_in,
                              void* d_out, int out_size) {
    const float* x   = (const float*)d_in[0];
    const float* Wz  = (const float*)d_in[1];
    const float* Ux  = (const float*)d_in[2];
    const float* b   = (const float*)d_in[3];
    const float* Wd  = (const float*)d_in[4];
    const float* bd  = (const float*)d_in[5];
    const int*   nit = (const int*)d_in[6];
    float* out = (float*)d_out;

    int rows = in_sizes[0] / IN_DIM;
    int grid = (rows + ROWS_PER_CTA - 1) / ROWS_PER_CTA;

    deq_mma_kernel<<<grid, THREADS, SMEM_TOTAL>>>(x, Wz, Ux, b, Wd, bd, nit, out, rows);
}

// round 14
// speedup vs baseline: 2.0894x; 2.0894x over previous
#include <cuda_runtime.h>
#include <cstdint>

// ==================== problem constants ====================
static constexpr int IN_DIM  = 64;
static constexpr int HID     = 128;
static constexpr int OUT_DIM = 64;

static constexpr int THREADS      = 128;   // 4 warps
static constexpr int MI           = 2;     // 2 x 16 = 32 rows per CTA
static constexpr int ROWS_PER_CTA = 16 * MI;
static constexpr int KS           = HID / 16;   // 8 k-steps of 16
// z exchange (fp16 A-frags), double buffered: (MI*KS) tiles x 32 slots x 16B
static constexpr int BUF_BYTES  = (MI * KS) * 32 * 16;        // 8 KB
static constexpr int OFF_INJ    = 2 * BUF_BYTES;              // 16 KB in
// inj: [warp:4][q:8][lane:32][16B]  (lane-major: conflict-free LDS.128/STS.128)
static constexpr int SMEM_TOTAL = OFF_INJ + 4 * 8 * 32 * 16;  // 32 KB

// ==================== small helpers ====================
__device__ __forceinline__ uint32_t pack_h2(float lo, float hi) {
    uint32_t d;
    asm("cvt.rn.f16x2.f32 %0, %1, %2;" : "=r"(d) : "f"(hi), "f"(lo));
    return d;
}
__device__ __forceinline__ uint32_t pack_h2_relu(float lo, float hi) {
    uint32_t d;
    asm("cvt.rn.relu.f16x2.f32 %0, %1, %2;" : "=r"(d) : "f"(hi), "f"(lo));
    return d;
}

// D(f32) += A(f16 m16n8k16) * B(f16)
__device__ __forceinline__ void mma_f16(float* d, const uint32_t* a, const uint32_t* b) {
    asm volatile(
        "mma.sync.aligned.m16n8k16.row.col.f32.f16.f16.f32 "
        "{%0,%1,%2,%3},{%4,%5,%6,%7},{%8,%9},{%0,%1,%2,%3};"
        : "+f"(d[0]), "+f"(d[1]), "+f"(d[2]), "+f"(d[3])
        : "r"(a[0]), "r"(a[1]), "r"(a[2]), "r"(a[3]), "r"(b[0]), "r"(b[1]));
}

// slot swizzle (involution; conflict-free LDS.128 loads & STS.64 stores)
__device__ __forceinline__ int swz(int l) { return l ^ (((l >> 3) & 1) << 2); }

// ==================== kernel ====================
__global__ void __launch_bounds__(THREADS, 4)
deq_mma_kernel(const float* __restrict__ x,
               const float* __restrict__ Wz,
               const float* __restrict__ Ux,
               const float* __restrict__ b,
               const float* __restrict__ Wd,
               const float* __restrict__ bd,
               const int*   __restrict__ nitp,
               float* __restrict__ out,
               int rows) {
    extern __shared__ char sm[];      // 2 x 8KB z bufs + 16KB inj (lane-major)
    const int tid  = threadIdx.x;
    const int w    = tid >> 5;        // warp owns col slice [32w, 32w+32)
    const int lane = tid & 31;
    const int g    = lane >> 2;       // row-in-8 (groupID)
    const int c    = lane & 3;        // threadID-in-group
    const int n_iters = *nitp;

    const long rowbase = (long)blockIdx.x * ROWS_PER_CTA;
    const uint32_t lanerd = (uint32_t)swz(lane) << 4;   // own 16B slot offset
    // inj slot for (q): lane-major, conflict-free (lanes stride 16B)
    char* injseg = sm + OFF_INJ + (uint32_t)w * (8 * 512) + (uint32_t)lane * 16u;

    // B-fragment register file (fp16x2 pairs). Wz: [s:8][ni:4] = 64 regs.
    // Reused: Ux [s:4][ni:4], Wd [s:8][ni:2].
    uint32_t B[32][2];

    // ---------------- load Ux B-frags (K=64 -> 4 k-steps) ----------------
#pragma unroll
    for (int s = 0; s < 4; s++)
#pragma unroll
        for (int ni = 0; ni < 4; ni++) {
            const float* src = Ux + (32 * w + 8 * ni + g) * IN_DIM + 16 * s + 2 * c;
            B[s * 4 + ni][0] = pack_h2(__ldg(src),     __ldg(src + 1));
            B[s * 4 + ni][1] = pack_h2(__ldg(src + 8), __ldg(src + 9));
        }

    // ---------------- inj = x @ Ux^T (in regs, then saved to smem) ----------------
    {
        float inj[MI][4][4];
#pragma unroll
        for (int mi = 0; mi < MI; mi++)
#pragma unroll
            for (int ni = 0; ni < 4; ni++)
#pragma unroll
                for (int r = 0; r < 4; r++) inj[mi][ni][r] = 0.0f;

#pragma unroll
        for (int s = 0; s < 4; s++) {
#pragma unroll
            for (int mi = 0; mi < MI; mi++) {
                uint32_t A[4];
                long r0 = rowbase + 16 * mi + g;
                long r1 = r0 + 8;
                const float* x0 = x + r0 * IN_DIM + 16 * s + 2 * c;
                const float* x1 = x + r1 * IN_DIM + 16 * s + 2 * c;
                float2 p0 = (r0 < rows) ? *reinterpret_cast<const float2*>(x0)     : make_float2(0.f, 0.f);
                float2 p1 = (r1 < rows) ? *reinterpret_cast<const float2*>(x1)     : make_float2(0.f, 0.f);
                float2 p2 = (r0 < rows) ? *reinterpret_cast<const float2*>(x0 + 8) : make_float2(0.f, 0.f);
                float2 p3 = (r1 < rows) ? *reinterpret_cast<const float2*>(x1 + 8) : make_float2(0.f, 0.f);
                A[0] = pack_h2(p0.x, p0.y);
                A[1] = pack_h2(p1.x, p1.y);
                A[2] = pack_h2(p2.x, p2.y);
                A[3] = pack_h2(p3.x, p3.y);
#pragma unroll
                for (int ni = 0; ni < 4; ni++)
                    mma_f16(inj[mi][ni], A, B[s * 4 + ni]);
            }
        }

        // add bias; save inj (f32, lane-major smem); scatter z1 = relu(inj) to buf 0
#pragma unroll
        for (int ni = 0; ni < 4; ni++) {
            float b0v = __ldg(b + 32 * w + 8 * ni + 2 * c);
            float b1v = __ldg(b + 32 * w + 8 * ni + 2 * c + 1);
#pragma unroll
            for (int mi = 0; mi < MI; mi++) {
                float4 v;
                v.x = inj[mi][ni][0] + b0v;
                v.y = inj[mi][ni][1] + b1v;
                v.z = inj[mi][ni][2] + b0v;
                v.w = inj[mi][ni][3] + b1v;
                *reinterpret_cast<float4*>(injseg + (uint32_t)((mi * 4 + ni) * 512)) = v;

                uint2 zv;
                zv.x = pack_h2_relu(v.x, v.y);   // rows g, g+8, cols 2c(+1)
                zv.y = pack_h2_relu(v.z, v.w);   // cols +8
                uint32_t tile = (uint32_t)(mi * KS + 2 * w + (ni >> 1));
                uint32_t addr = tile * 512u + lanerd + ((uint32_t)(ni & 1) << 3);
                *reinterpret_cast<uint2*>(sm + addr) = zv;
            }
        }
    }

    // ---------------- load Wz B-frags (once; K=128 -> 8 k-steps) ----------------
#pragma unroll
    for (int s = 0; s < KS; s++)
#pragma unroll
        for (int ni = 0; ni < 4; ni++) {
            const float* src = Wz + (32 * w + 8 * ni + g) * HID + 16 * s + 2 * c;
            B[s * 4 + ni][0] = pack_h2(__ldg(src),     __ldg(src + 1));
            B[s * 4 + ni][1] = pack_h2(__ldg(src + 8), __ldg(src + 9));
        }
    __syncthreads();   // z1 scatter visible to all warps

    // ---------------- fixed-point loop: mi-split pipeline, one sync/iter ----------------
    char* rd = sm;
    char* wr = sm + BUF_BYTES;
    for (int it = 1; it < n_iters; it++) {
#pragma unroll
        for (int mi = 0; mi < MI; mi++) {
            // acc starts at inj (lane-major smem read; exact f32)
            float acc[4][4];
#pragma unroll
            for (int ni = 0; ni < 4; ni++) {
                float4 v = *reinterpret_cast<const float4*>(
                    injseg + (uint32_t)((mi * 4 + ni) * 512));
                acc[ni][0] = v.x; acc[ni][1] = v.y; acc[ni][2] = v.z; acc[ni][3] = v.w;
            }

            const char* rdm = rd + (uint32_t)(mi * KS * 512);
#pragma unroll
            for (int s = 0; s < KS; s++) {
                uint4 a = *reinterpret_cast<const uint4*>(rdm + (uint32_t)(s * 512) + lanerd);
                uint32_t A[4] = {a.x, a.y, a.z, a.w};
#pragma unroll
                for (int ni = 0; ni < 4; ni++)
                    mma_f16(acc[ni], A, B[s * 4 + ni]);
            }

            // epilogue for this mi (stores overlap next mi's / other CTAs' MMAs)
            char* wrm = wr + (uint32_t)(mi * KS * 512);
#pragma unroll
            for (int ni = 0; ni < 4; ni++) {
                uint2 v;
                v.x = pack_h2_relu(acc[ni][0], acc[ni][1]);
                v.y = pack_h2_relu(acc[ni][2], acc[ni][3]);
                uint32_t tile = (uint32_t)(2 * w + (ni >> 1));
                uint32_t addr = tile * 512u + lanerd + ((uint32_t)(ni & 1) << 3);
                *reinterpret_cast<uint2*>(wrm + addr) = v;
            }
        }
        __syncthreads();
        char* t = rd; rd = wr; wr = t;
    }

    // ---------------- decoder: out = z @ Wd^T + bd ----------------
    // warp w computes cols [16w, 16w+16): ni 0..1
#pragma unroll
    for (int s = 0; s < KS; s++)
#pragma unroll
        for (int ni = 0; ni < 2; ni++) {
            const float* src = Wd + (16 * w + 8 * ni + g) * HID + 16 * s + 2 * c;
            B[s * 2 + ni][0] = pack_h2(__ldg(src),     __ldg(src + 1));
            B[s * 2 + ni][1] = pack_h2(__ldg(src + 8), __ldg(src + 9));
        }

#pragma unroll
    for (int mi = 0; mi < MI; mi++) {
        float acc2[2][4];
#pragma unroll
        for (int ni = 0; ni < 2; ni++)
#pragma unroll
            for (int r = 0; r < 4; r++) acc2[ni][r] = 0.0f;

        const char* rdm = rd + (uint32_t)(mi * KS * 512);
#pragma unroll
        for (int s = 0; s < KS; s++) {
            uint4 a = *reinterpret_cast<const uint4*>(rdm + (uint32_t)(s * 512) + lanerd);
            uint32_t A[4] = {a.x, a.y, a.z, a.w};
#pragma unroll
            for (int ni = 0; ni < 2; ni++)
                mma_f16(acc2[ni], A, B[s * 2 + ni]);
        }

        long r0 = rowbase + 16 * mi + g;
        long r1 = r0 + 8;
#pragma unroll
        for (int ni = 0; ni < 2; ni++) {
            int colb = 16 * w + 8 * ni + 2 * c;
            float bd0 = __ldg(bd + colb);
            float bd1 = __ldg(bd + colb + 1);
            if (r0 < rows) {
                float2 v0 = make_float2(acc2[ni][0] + bd0, acc2[ni][1] + bd1);
                *reinterpret_cast<float2*>(out + r0 * OUT_DIM + colb) = v0;
            }
            if (r1 < rows) {
                float2 v1 = make_float2(acc2[ni][2] + bd0, acc2[ni][3] + bd1);
                *reinterpret_cast<float2*>(out + r1 * OUT_DIM + colb) = v1;
            }
        }
    }
}

// ==================== launch ====================
extern "C" void kernel_launch(void* const* d_in, const int* in_sizes, int n_in,
                              void* d_out, int out_size) {
    const float* x   = (const float*)d_in[0];
    const float* Wz  = (const float*)d_in[1];
    const float* Ux  = (const float*)d_in[2];
    const float* b   = (const float*)d_in[3];
    const float* Wd  = (const float*)d_in[4];
    const float* bd  = (const float*)d_in[5];
    const int*   nit = (const int*)d_in[6];
    float* out = (float*)d_out;

    int rows = in_sizes[0] / IN_DIM;
    int grid = (rows + ROWS_PER_CTA - 1) / ROWS_PER_CTA;

    deq_mma_kernel<<<grid, THREADS, SMEM_TOTAL>>>(x, Wz, Ux, b, Wd, bd, nit, out, rows);
}

// round 15
// speedup vs baseline: 2.2134x; 1.0593x over previous
#include <cuda_runtime.h>
#include <cstdint>

// ==================== problem constants ====================
static constexpr int IN_DIM  = 64;
static constexpr int HID     = 128;
static constexpr int OUT_DIM = 64;

static constexpr int THREADS      = 128;   // 4 warps
static constexpr int MI           = 2;     // 2 x 16 = 32 rows per CTA
static constexpr int ROWS_PER_CTA = 16 * MI;
static constexpr int KS           = HID / 16;   // 8 k-steps of 16
// z exchange (fp16 A-frags), double buffered: (MI*KS) tiles x 32 slots x 16B
static constexpr int BUF_BYTES  = (MI * KS) * 32 * 16;   // 8 KB
static constexpr int SMEM_TOTAL = 2 * BUF_BYTES;         // 16 KB

// ==================== small helpers ====================
__device__ __forceinline__ uint32_t pack_h2(float lo, float hi) {
    uint32_t d;
    asm("cvt.rn.f16x2.f32 %0, %1, %2;" : "=r"(d) : "f"(hi), "f"(lo));
    return d;
}
__device__ __forceinline__ uint32_t pack_h2_relu(float lo, float hi) {
    uint32_t d;
    asm("cvt.rn.relu.f16x2.f32 %0, %1, %2;" : "=r"(d) : "f"(hi), "f"(lo));
    return d;
}

// D(f32) += A(f16 m16n8k16) * B(f16)
__device__ __forceinline__ void mma_f16(float* d, const uint32_t* a, const uint32_t* b) {
    asm volatile(
        "mma.sync.aligned.m16n8k16.row.col.f32.f16.f16.f32 "
        "{%0,%1,%2,%3},{%4,%5,%6,%7},{%8,%9},{%0,%1,%2,%3};"
        : "+f"(d[0]), "+f"(d[1]), "+f"(d[2]), "+f"(d[3])
        : "r"(a[0]), "r"(a[1]), "r"(a[2]), "r"(a[3]), "r"(b[0]), "r"(b[1]));
}

// slot swizzle (involution; conflict-free LDS.128 loads & STS.128 stores)
__device__ __forceinline__ int swz(int l) { return l ^ (((l >> 3) & 1) << 2); }

// ==================== kernel ====================
__global__ void __launch_bounds__(THREADS, 4)
deq_mma_kernel(const float* __restrict__ x,
               const float* __restrict__ Wz,
               const float* __restrict__ Ux,
               const float* __restrict__ b,
               const float* __restrict__ Wd,
               const float* __restrict__ bd,
               const int*   __restrict__ nitp,
               float* __restrict__ out,
               int rows) {
    extern __shared__ char sm[];      // 2 x 8KB z A-frag buffers
    const int tid  = threadIdx.x;
    const int w    = tid >> 5;        // warp owns col slice [32w, 32w+32)
    const int lane = tid & 31;
    const int g    = lane >> 2;       // row-in-8 (groupID)
    const int c    = lane & 3;        // threadID-in-group
    const int n_iters = *nitp;

    const long rowbase = (long)blockIdx.x * ROWS_PER_CTA;
    const uint32_t lanerd = (uint32_t)swz(lane) << 4;   // own 16B slot offset

    // B-fragment register file (fp16x2 pairs). Wz: [s:8][ni:4] = 64 regs.
    // Reused: Ux [s:4][ni:4], Wd [s:8][ni:2].
    uint32_t B[32][2];

    // ---------------- load Ux B-frags (K=64 -> 4 k-steps) ----------------
#pragma unroll
    for (int s = 0; s < 4; s++)
#pragma unroll
        for (int ni = 0; ni < 4; ni++) {
            const float* src = Ux + (32 * w + 8 * ni + g) * IN_DIM + 16 * s + 2 * c;
            B[s * 4 + ni][0] = pack_h2(__ldg(src),     __ldg(src + 1));
            B[s * 4 + ni][1] = pack_h2(__ldg(src + 8), __ldg(src + 9));
        }

    // ---------------- inj = x @ Ux^T + b (stays in 32 registers) ----------------
    float inj[MI][4][4];
#pragma unroll
    for (int mi = 0; mi < MI; mi++)
#pragma unroll
        for (int ni = 0; ni < 4; ni++)
#pragma unroll
            for (int r = 0; r < 4; r++) inj[mi][ni][r] = 0.0f;

#pragma unroll
    for (int s = 0; s < 4; s++) {
#pragma unroll
        for (int mi = 0; mi < MI; mi++) {
            uint32_t A[4];
            long r0 = rowbase + 16 * mi + g;
            long r1 = r0 + 8;
            const float* x0 = x + r0 * IN_DIM + 16 * s + 2 * c;
            const float* x1 = x + r1 * IN_DIM + 16 * s + 2 * c;
            float2 p0 = (r0 < rows) ? *reinterpret_cast<const float2*>(x0)     : make_float2(0.f, 0.f);
            float2 p1 = (r1 < rows) ? *reinterpret_cast<const float2*>(x1)     : make_float2(0.f, 0.f);
            float2 p2 = (r0 < rows) ? *reinterpret_cast<const float2*>(x0 + 8) : make_float2(0.f, 0.f);
            float2 p3 = (r1 < rows) ? *reinterpret_cast<const float2*>(x1 + 8) : make_float2(0.f, 0.f);
            A[0] = pack_h2(p0.x, p0.y);
            A[1] = pack_h2(p1.x, p1.y);
            A[2] = pack_h2(p2.x, p2.y);
            A[3] = pack_h2(p3.x, p3.y);
#pragma unroll
            for (int ni = 0; ni < 4; ni++)
                mma_f16(inj[mi][ni], A, B[s * 4 + ni]);
        }
    }

    // add bias; scatter z1 = relu(inj) into buffer 0 (one STS.128 per 16-col tile)
#pragma unroll
    for (int ni = 0; ni < 4; ni++) {
        float b0v = __ldg(b + 32 * w + 8 * ni + 2 * c);
        float b1v = __ldg(b + 32 * w + 8 * ni + 2 * c + 1);
#pragma unroll
        for (int mi = 0; mi < MI; mi++) {
            inj[mi][ni][0] += b0v;
            inj[mi][ni][1] += b1v;
            inj[mi][ni][2] += b0v;
            inj[mi][ni][3] += b1v;
        }
    }
#pragma unroll
    for (int mi = 0; mi < MI; mi++)
#pragma unroll
        for (int p = 0; p < 2; p++) {
            uint4 v;
            v.x = pack_h2_relu(inj[mi][2 * p][0], inj[mi][2 * p][1]);
            v.y = pack_h2_relu(inj[mi][2 * p][2], inj[mi][2 * p][3]);
            v.z = pack_h2_relu(inj[mi][2 * p + 1][0], inj[mi][2 * p + 1][1]);
            v.w = pack_h2_relu(inj[mi][2 * p + 1][2], inj[mi][2 * p + 1][3]);
            uint32_t tile = (uint32_t)(mi * KS + 2 * w + p);
            *reinterpret_cast<uint4*>(sm + tile * 512u + lanerd) = v;
        }

    // ---------------- load Wz B-frags (once; K=128 -> 8 k-steps) ----------------
#pragma unroll
    for (int s = 0; s < KS; s++)
#pragma unroll
        for (int ni = 0; ni < 4; ni++) {
            const float* src = Wz + (32 * w + 8 * ni + g) * HID + 16 * s + 2 * c;
            B[s * 4 + ni][0] = pack_h2(__ldg(src),     __ldg(src + 1));
            B[s * 4 + ni][1] = pack_h2(__ldg(src + 8), __ldg(src + 9));
        }
    __syncthreads();   // z1 scatter visible to all warps

    // ---------------- fixed-point loop: mi-split pipeline, one sync/iter ----------------
    uint32_t rdo = 0;                 // read-buffer byte offset (0 or BUF_BYTES)
    for (int it = 1; it < n_iters; it++) {
#pragma unroll
        for (int mi = 0; mi < MI; mi++) {
            // acc starts at inj (injection folded into accumulator init)
            float acc[4][4];
#pragma unroll
            for (int ni = 0; ni < 4; ni++)
#pragma unroll
                for (int r = 0; r < 4; r++) acc[ni][r] = inj[mi][ni][r];

            const char* rdm = sm + rdo + (uint32_t)(mi * KS * 512) + lanerd;
#pragma unroll
            for (int s = 0; s < KS; s++) {
                uint4 a = *reinterpret_cast<const uint4*>(rdm + (uint32_t)(s * 512));
                uint32_t A[4] = {a.x, a.y, a.z, a.w};
#pragma unroll
                for (int ni = 0; ni < 4; ni++)
                    mma_f16(acc[ni], A, B[s * 4 + ni]);
            }

            // epilogue for this mi: 2 packed STS.128 (overlap other work)
            char* wrm = sm + (rdo ^ BUF_BYTES) + (uint32_t)(mi * KS * 512) + lanerd;
#pragma unroll
            for (int p = 0; p < 2; p++) {
                uint4 v;
                v.x = pack_h2_relu(acc[2 * p][0], acc[2 * p][1]);
                v.y = pack_h2_relu(acc[2 * p][2], acc[2 * p][3]);
                v.z = pack_h2_relu(acc[2 * p + 1][0], acc[2 * p + 1][1]);
                v.w = pack_h2_relu(acc[2 * p + 1][2], acc[2 * p + 1][3]);
                *reinterpret_cast<uint4*>(wrm + (uint32_t)((2 * w + p) * 512)) = v;
            }
        }
        __syncthreads();
        rdo ^= BUF_BYTES;
    }

    // ---------------- decoder: out = z @ Wd^T + bd ----------------
    // warp w computes cols [16w, 16w+16): ni 0..1
#pragma unroll
    for (int s = 0; s < KS; s++)
#pragma unroll
        for (int ni = 0; ni < 2; ni++) {
            const float* src = Wd + (16 * w + 8 * ni + g) * HID + 16 * s + 2 * c;
            B[s * 2 + ni][0] = pack_h2(__ldg(src),     __ldg(src + 1));
            B[s * 2 + ni][1] = pack_h2(__ldg(src + 8), __ldg(src + 9));
        }

#pragma unroll
    for (int mi = 0; mi < MI; mi++) {
        float acc2[2][4];
#pragma unroll
        for (int ni = 0; ni < 2; ni++)
#pragma unroll
            for (int r = 0; r < 4; r++) acc2[ni][r] = 0.0f;

        const char* rdm = sm + rdo + (uint32_t)(mi * KS * 512) + lanerd;
#pragma unroll
        for (int s = 0; s < KS; s++) {
            uint4 a = *reinterpret_cast<const uint4*>(rdm + (uint32_t)(s * 512));
            uint32_t A[4] = {a.x, a.y, a.z, a.w};
#pragma unroll
            for (int ni = 0; ni < 2; ni++)
                mma_f16(acc2[ni], A, B[s * 2 + ni]);
        }

        long r0 = rowbase + 16 * mi + g;
        long r1 = r0 + 8;
#pragma unroll
        for (int ni = 0; ni < 2; ni++) {
            int colb = 16 * w + 8 * ni + 2 * c;
            float bd0 = __ldg(bd + colb);
            float bd1 = __ldg(bd + colb + 1);
            if (r0 < rows) {
                float2 v0 = make_float2(acc2[ni][0] + bd0, acc2[ni][1] + bd1);
                *reinterpret_cast<float2*>(out + r0 * OUT_DIM + colb) = v0;
            }
            if (r1 < rows) {
                float2 v1 = make_float2(acc2[ni][2] + bd0, acc2[ni][3] + bd1);
                *reinterpret_cast<float2*>(out + r1 * OUT_DIM + colb) = v1;
            }
        }
    }
}

// ==================== launch ====================
extern "C" void kernel_launch(void* const* d_in, const int* in_sizes, int n_in,
                              void* d_out, int out_size) {
    const float* x   = (const float*)d_in[0];
    const float* Wz  = (const float*)d_in[1];
    const float* Ux  = (const float*)d_in[2];
    const float* b   = (const float*)d_in[3];
    const float* Wd  = (const float*)d_in[4];
    const float* bd  = (const float*)d_in[5];
    const int*   nit = (const int*)d_in[6];
    float* out = (float*)d_out;

    int rows = in_sizes[0] / IN_DIM;
    int grid = (rows + ROWS_PER_CTA - 1) / ROWS_PER_CTA;

    deq_mma_kernel<<<grid, THREADS, SMEM_TOTAL>>>(x, Wz, Ux, b, Wd, bd, nit, out, rows);
}

// round 16
// speedup vs baseline: 2.3510x; 1.0622x over previous
#include <cuda_runtime.h>
#include <cstdint>

// ==================== problem constants ====================
static constexpr int IN_DIM  = 64;
static constexpr int HID     = 128;
static constexpr int OUT_DIM = 64;

static constexpr int THREADS      = 128;   // 4 warps = 2 independent pairs
static constexpr int ROWS_PER_CTA = 64;    // pair p owns rows [32p, 32p+32)
static constexpr int KS           = HID / 16;   // 8 k-steps of 16
// z exchange (fp16 A-frags): 4 row-tiles x 8 k-tiles x 32 slots x 16B, x2 buffers
static constexpr int BUF_BYTES  = 4 * KS * 32 * 16;      // 16 KB
static constexpr int SMEM_TOTAL = 2 * BUF_BYTES;         // 32 KB

// ==================== small helpers ====================
__device__ __forceinline__ uint32_t pack_h2(float lo, float hi) {
    uint32_t d;
    asm("cvt.rn.f16x2.f32 %0, %1, %2;" : "=r"(d) : "f"(hi), "f"(lo));
    return d;
}
__device__ __forceinline__ uint32_t pack_h2_relu(float lo, float hi) {
    uint32_t d;
    asm("cvt.rn.relu.f16x2.f32 %0, %1, %2;" : "=r"(d) : "f"(hi), "f"(lo));
    return d;
}

// D(f32) = A*B + D   (accumulate in place)
__device__ __forceinline__ void mma_f16(float* d, const uint32_t* a, const uint32_t* b) {
    asm volatile(
        "mma.sync.aligned.m16n8k16.row.col.f32.f16.f16.f32 "
        "{%0,%1,%2,%3},{%4,%5,%6,%7},{%8,%9},{%0,%1,%2,%3};"
        : "+f"(d[0]), "+f"(d[1]), "+f"(d[2]), "+f"(d[3])
        : "r"(a[0]), "r"(a[1]), "r"(a[2]), "r"(a[3]), "r"(b[0]), "r"(b[1]));
}
// D(f32) = A*B + C   (distinct C: folds inj without MOVs)
__device__ __forceinline__ void mma_f16_c(float* d, const uint32_t* a, const uint32_t* b,
                                          const float* cc) {
    asm volatile(
        "mma.sync.aligned.m16n8k16.row.col.f32.f16.f16.f32 "
        "{%0,%1,%2,%3},{%4,%5,%6,%7},{%8,%9},{%10,%11,%12,%13};"
        : "=f"(d[0]), "=f"(d[1]), "=f"(d[2]), "=f"(d[3])
        : "r"(a[0]), "r"(a[1]), "r"(a[2]), "r"(a[3]), "r"(b[0]), "r"(b[1]),
          "f"(cc[0]), "f"(cc[1]), "f"(cc[2]), "f"(cc[3]));
}

// slot swizzle (involution; conflict-free LDS.128 loads & STS.128 stores)
__device__ __forceinline__ int swz(int l) { return l ^ (((l >> 3) & 1) << 2); }

#define PAIR_BAR(p) asm volatile("bar.sync %0, 64;" :: "r"(1 + (p)) : "memory")

// ==================== kernel ====================
__global__ void __launch_bounds__(THREADS, 2)
deq_mma_kernel(const float* __restrict__ x,
               const float* __restrict__ Wz,
               const float* __restrict__ Ux,
               const float* __restrict__ b,
               const float* __restrict__ Wd,
               const float* __restrict__ bd,
               const int*   __restrict__ nitp,
               float* __restrict__ out,
               int rows) {
    extern __shared__ char sm[];      // 2 x 16KB z A-frag buffers
    const int tid  = threadIdx.x;
    const int w    = tid >> 5;
    const int p    = w >> 1;          // pair: owns rows [32p, 32p+32)
    const int h    = w & 1;           // col half: [64h, 64h+64)
    const int lane = tid & 31;
    const int g    = lane >> 2;       // row-in-8 (groupID)
    const int c    = lane & 3;        // threadID-in-group
    const int n_iters = *nitp;

    const long rowpair = (long)blockIdx.x * ROWS_PER_CTA + 32 * p;
    const uint32_t lanerd = (uint32_t)swz(lane) << 4;   // own 16B slot offset

    // B-fragment register file (fp16x2 pairs). Wz: [s:8][ni:8] = 128 regs.
    // Reused: Ux [s:4][ni:8], Wd [s:8][ni:4].
    uint32_t B[64][2];

    // ---------------- load Ux B-frags (K=64 -> 4 k-steps; 8 ni tiles) ----------------
#pragma unroll
    for (int s = 0; s < 4; s++)
#pragma unroll
        for (int ni = 0; ni < 8; ni++) {
            const float* src = Ux + (64 * h + 8 * ni + g) * IN_DIM + 16 * s + 2 * c;
            B[s * 8 + ni][0] = pack_h2(__ldg(src),     __ldg(src + 1));
            B[s * 8 + ni][1] = pack_h2(__ldg(src + 8), __ldg(src + 9));
        }

    // ---------------- inj = x @ Ux^T + b (stays in 64 registers) ----------------
    float inj[2][8][4];
#pragma unroll
    for (int mi = 0; mi < 2; mi++)
#pragma unroll
        for (int ni = 0; ni < 8; ni++)
#pragma unroll
            for (int r = 0; r < 4; r++) inj[mi][ni][r] = 0.0f;

#pragma unroll
    for (int s = 0; s < 4; s++) {
#pragma unroll
        for (int mi = 0; mi < 2; mi++) {
            uint32_t A[4];
            long r0 = rowpair + 16 * mi + g;
            long r1 = r0 + 8;
            const float* x0 = x + r0 * IN_DIM + 16 * s + 2 * c;
            const float* x1 = x + r1 * IN_DIM + 16 * s + 2 * c;
            float2 p0 = (r0 < rows) ? *reinterpret_cast<const float2*>(x0)     : make_float2(0.f, 0.f);
            float2 p1 = (r1 < rows) ? *reinterpret_cast<const float2*>(x1)     : make_float2(0.f, 0.f);
            float2 p2 = (r0 < rows) ? *reinterpret_cast<const float2*>(x0 + 8) : make_float2(0.f, 0.f);
            float2 p3 = (r1 < rows) ? *reinterpret_cast<const float2*>(x1 + 8) : make_float2(0.f, 0.f);
            A[0] = pack_h2(p0.x, p0.y);
            A[1] = pack_h2(p1.x, p1.y);
            A[2] = pack_h2(p2.x, p2.y);
            A[3] = pack_h2(p3.x, p3.y);
#pragma unroll
            for (int ni = 0; ni < 8; ni++)
                mma_f16(inj[mi][ni], A, B[s * 8 + ni]);
        }
    }

    // add bias; scatter z1 = relu(inj) into buffer 0 (packed STS.128)
#pragma unroll
    for (int ni = 0; ni < 8; ni++) {
        float b0v = __ldg(b + 64 * h + 8 * ni + 2 * c);
        float b1v = __ldg(b + 64 * h + 8 * ni + 2 * c + 1);
#pragma unroll
        for (int mi = 0; mi < 2; mi++) {
            inj[mi][ni][0] += b0v;
            inj[mi][ni][1] += b1v;
            inj[mi][ni][2] += b0v;
            inj[mi][ni][3] += b1v;
        }
    }
#pragma unroll
    for (int mi = 0; mi < 2; mi++)
#pragma unroll
        for (int t = 0; t < 4; t++) {   // 16-col tile t holds ni=2t, 2t+1
            uint4 v;
            v.x = pack_h2_relu(inj[mi][2 * t][0], inj[mi][2 * t][1]);
            v.y = pack_h2_relu(inj[mi][2 * t][2], inj[mi][2 * t][3]);
            v.z = pack_h2_relu(inj[mi][2 * t + 1][0], inj[mi][2 * t + 1][1]);
            v.w = pack_h2_relu(inj[mi][2 * t + 1][2], inj[mi][2 * t + 1][3]);
            uint32_t tile = (uint32_t)((2 * p + mi) * KS + 4 * h + t);
            *reinterpret_cast<uint4*>(sm + tile * 512u + lanerd) = v;
        }

    // ---------------- load Wz B-frags (once; K=128 -> 8 k-steps; 8 ni) ----------------
#pragma unroll
    for (int s = 0; s < KS; s++)
#pragma unroll
        for (int ni = 0; ni < 8; ni++) {
            const float* src = Wz + (64 * h + 8 * ni + g) * HID + 16 * s + 2 * c;
            B[s * 8 + ni][0] = pack_h2(__ldg(src),     __ldg(src + 1));
            B[s * 8 + ni][1] = pack_h2(__ldg(src + 8), __ldg(src + 9));
        }
    PAIR_BAR(p);   // z1 scatter visible within pair (only the pair reads these rows)

    // ---------------- fixed-point loop: pair-local sync, one bar/iter ----------------
    uint32_t rdo = 0;                 // read-buffer byte offset (0 or BUF_BYTES)
    for (int it = 1; it < n_iters; it++) {
#pragma unroll
        for (int mi = 0; mi < 2; mi++) {
            float acc[8][4];
            const char* rdm = sm + rdo + (uint32_t)((2 * p + mi) * KS * 512) + lanerd;
            // s = 0: acc = A*B + inj (no MOV init)
            {
                uint4 a = *reinterpret_cast<const uint4*>(rdm);
                uint32_t A[4] = {a.x, a.y, a.z, a.w};
#pragma unroll
                for (int ni = 0; ni < 8; ni++)
                    mma_f16_c(acc[ni], A, B[ni], inj[mi][ni]);
            }
#pragma unroll
            for (int s = 1; s < KS; s++) {
                uint4 a = *reinterpret_cast<const uint4*>(rdm + (uint32_t)(s * 512));
                uint32_t A[4] = {a.x, a.y, a.z, a.w};
#pragma unroll
                for (int ni = 0; ni < 8; ni++)
                    mma_f16(acc[ni], A, B[s * 8 + ni]);
            }

            // epilogue for this mi: 4 packed STS.128
            char* wrm = sm + (rdo ^ BUF_BYTES) + (uint32_t)((2 * p + mi) * KS * 512) + lanerd;
#pragma unroll
            for (int t = 0; t < 4; t++) {
                uint4 v;
                v.x = pack_h2_relu(acc[2 * t][0], acc[2 * t][1]);
                v.y = pack_h2_relu(acc[2 * t][2], acc[2 * t][3]);
                v.z = pack_h2_relu(acc[2 * t + 1][0], acc[2 * t + 1][1]);
                v.w = pack_h2_relu(acc[2 * t + 1][2], acc[2 * t + 1][3]);
                *reinterpret_cast<uint4*>(wrm + (uint32_t)((4 * h + t) * 512)) = v;
            }
        }
        PAIR_BAR(p);
        rdo ^= BUF_BYTES;
    }

    // ---------------- decoder: out = z @ Wd^T + bd ----------------
    // warp (p,h) computes cols [32h, 32h+32) for its pair's rows: ni 0..3
#pragma unroll
    for (int s = 0; s < KS; s++)
#pragma unroll
        for (int ni = 0; ni < 4; ni++) {
            const float* src = Wd + (32 * h + 8 * ni + g) * HID + 16 * s + 2 * c;
            B[s * 4 + ni][0] = pack_h2(__ldg(src),     __ldg(src + 1));
            B[s * 4 + ni][1] = pack_h2(__ldg(src + 8), __ldg(src + 9));
        }

#pragma unroll
    for (int mi = 0; mi < 2; mi++) {
        float acc2[4][4];
#pragma unroll
        for (int ni = 0; ni < 4; ni++)
#pragma unroll
            for (int r = 0; r < 4; r++) acc2[ni][r] = 0.0f;

        const char* rdm = sm + rdo + (uint32_t)((2 * p + mi) * KS * 512) + lanerd;
#pragma unroll
        for (int s = 0; s < KS; s++) {
            uint4 a = *reinterpret_cast<const uint4*>(rdm + (uint32_t)(s * 512));
            uint32_t A[4] = {a.x, a.y, a.z, a.w};
#pragma unroll
            for (int ni = 0; ni < 4; ni++)
                mma_f16(acc2[ni], A, B[s * 4 + ni]);
        }

        long r0 = rowpair + 16 * mi + g;
        long r1 = r0 + 8;
#pragma unroll
        for (int ni = 0; ni < 4; ni++) {
            int colb = 32 * h + 8 * ni + 2 * c;
            float bd0 = __ldg(bd + colb);
            float bd1 = __ldg(bd + colb + 1);
            if (r0 < rows) {
                float2 v0 = make_float2(acc2[ni][0] + bd0, acc2[ni][1] + bd1);
                *reinterpret_cast<float2*>(out + r0 * OUT_DIM + colb) = v0;
            }
            if (r1 < rows) {
                float2 v1 = make_float2(acc2[ni][2] + bd0, acc2[ni][3] + bd1);
                *reinterpret_cast<float2*>(out + r1 * OUT_DIM + colb) = v1;
            }
        }
    }
}

// ==================== launch ====================
extern "C" void kernel_launch(void* const* d_in, const int* in_sizes, int n_in,
                              void* d_out, int out_size) {
    const float* x   = (const float*)d_in[0];
    const float* Wz  = (const float*)d_in[1];
    const float* Ux  = (const float*)d_in[2];
    const float* b   = (const float*)d_in[3];
    const float* Wd  = (const float*)d_in[4];
    const float* bd  = (const float*)d_in[5];
    const int*   nit = (const int*)d_in[6];
    float* out = (float*)d_out;

    int rows = in_sizes[0] / IN_DIM;
    int grid = (rows + ROWS_PER_CTA - 1) / ROWS_PER_CTA;

    deq_mma_kernel<<<grid, THREADS, SMEM_TOTAL>>>(x, Wz, Ux, b, Wd, bd, nit, out, rows);
}

// round 17
// speedup vs baseline: 2.5485x; 1.0840x over previous
#include <cuda_runtime.h>
#include <cstdint>

// ==================== problem constants ====================
static constexpr int IN_DIM  = 64;
static constexpr int HID     = 128;
static constexpr int OUT_DIM = 64;

static constexpr int THREADS      = 128;   // 4 warps
static constexpr int MI           = 8;     // 8 x 16 = 128 rows per CTA
static constexpr int ROWS_PER_CTA = 16 * MI;
static constexpr int KS           = HID / 16;   // 8 k-steps of 16
// z exchange (fp16 A-frags), double buffered: (MI*KS) tiles x 32 slots x 16B
static constexpr int BUF_BYTES  = (MI * KS) * 32 * 16;   // 32 KB
static constexpr int SMEM_TOTAL = 2 * BUF_BYTES;         // 64 KB

// ==================== small helpers ====================
__device__ __forceinline__ uint32_t pack_h2(float lo, float hi) {
    uint32_t d;
    asm("cvt.rn.f16x2.f32 %0, %1, %2;" : "=r"(d) : "f"(hi), "f"(lo));
    return d;
}
__device__ __forceinline__ uint32_t pack_h2_relu(float lo, float hi) {
    uint32_t d;
    asm("cvt.rn.relu.f16x2.f32 %0, %1, %2;" : "=r"(d) : "f"(hi), "f"(lo));
    return d;
}

// D(f32) = A*B + D   (accumulate in place)
__device__ __forceinline__ void mma_f16(float* d, const uint32_t* a, const uint32_t* b) {
    asm volatile(
        "mma.sync.aligned.m16n8k16.row.col.f32.f16.f16.f32 "
        "{%0,%1,%2,%3},{%4,%5,%6,%7},{%8,%9},{%0,%1,%2,%3};"
        : "+f"(d[0]), "+f"(d[1]), "+f"(d[2]), "+f"(d[3])
        : "r"(a[0]), "r"(a[1]), "r"(a[2]), "r"(a[3]), "r"(b[0]), "r"(b[1]));
}
// D(f32) = A*B + C   (distinct C: folds inj init without MOVs)
__device__ __forceinline__ void mma_f16_c(float* d, const uint32_t* a, const uint32_t* b,
                                          const float* cc) {
    asm volatile(
        "mma.sync.aligned.m16n8k16.row.col.f32.f16.f16.f32 "
        "{%0,%1,%2,%3},{%4,%5,%6,%7},{%8,%9},{%10,%11,%12,%13};"
        : "=f"(d[0]), "=f"(d[1]), "=f"(d[2]), "=f"(d[3])
        : "r"(a[0]), "r"(a[1]), "r"(a[2]), "r"(a[3]), "r"(b[0]), "r"(b[1]),
          "f"(cc[0]), "f"(cc[1]), "f"(cc[2]), "f"(cc[3]));
}

// slot swizzle (involution; conflict-free LDS.128 loads & STS.128 stores)
__device__ __forceinline__ int swz(int l) { return l ^ (((l >> 3) & 1) << 2); }

// ==================== kernel ====================
__global__ void __launch_bounds__(THREADS, 2)
deq_mma_kernel(const float* __restrict__ x,
               const float* __restrict__ Wz,
               const float* __restrict__ Ux,
               const float* __restrict__ b,
               const float* __restrict__ Wd,
               const float* __restrict__ bd,
               const int*   __restrict__ nitp,
               float* __restrict__ out,
               int rows) {
    extern __shared__ char sm[];      // 2 x 32KB fp16 z A-frag buffers
    const int tid  = threadIdx.x;
    const int w    = tid >> 5;        // warp owns col slice [32w, 32w+32)
    const int lane = tid & 31;
    const int g    = lane >> 2;       // row-in-8 (groupID)
    const int c    = lane & 3;        // threadID-in-group
    const int n_iters = *nitp;

    const long rowbase = (long)blockIdx.x * ROWS_PER_CTA;
    const uint32_t lanerd = (uint32_t)swz(lane) << 4;   // own 16B slot offset

    // B-fragment register file (fp16x2 pairs). Wz: [s:8][ni:4] = 64 regs.
    // Reused: Ux [s:4][ni:4], Wd [s:8][ni:2].
    uint32_t B[32][2];

    // ---------------- load Ux B-frags (K=64 -> 4 k-steps) ----------------
#pragma unroll
    for (int s = 0; s < 4; s++)
#pragma unroll
        for (int ni = 0; ni < 4; ni++) {
            const float* src = Ux + (32 * w + 8 * ni + g) * IN_DIM + 16 * s + 2 * c;
            B[s * 4 + ni][0] = pack_h2(__ldg(src),     __ldg(src + 1));
            B[s * 4 + ni][1] = pack_h2(__ldg(src + 8), __ldg(src + 9));
        }

    // ---------------- inj = x @ Ux^T (straight into inj regs) ----------------
    float inj[MI][4][4];
#pragma unroll
    for (int mi = 0; mi < MI; mi++)
#pragma unroll
        for (int ni = 0; ni < 4; ni++)
#pragma unroll
            for (int r = 0; r < 4; r++) inj[mi][ni][r] = 0.0f;

#pragma unroll
    for (int s = 0; s < 4; s++) {
#pragma unroll
        for (int mi = 0; mi < MI; mi++) {
            uint32_t A[4];
            long r0 = rowbase + 16 * mi + g;
            long r1 = r0 + 8;
            const float* x0 = x + r0 * IN_DIM + 16 * s + 2 * c;
            const float* x1 = x + r1 * IN_DIM + 16 * s + 2 * c;
            float2 p0 = (r0 < rows) ? *reinterpret_cast<const float2*>(x0)     : make_float2(0.f, 0.f);
            float2 p1 = (r1 < rows) ? *reinterpret_cast<const float2*>(x1)     : make_float2(0.f, 0.f);
            float2 p2 = (r0 < rows) ? *reinterpret_cast<const float2*>(x0 + 8) : make_float2(0.f, 0.f);
            float2 p3 = (r1 < rows) ? *reinterpret_cast<const float2*>(x1 + 8) : make_float2(0.f, 0.f);
            A[0] = pack_h2(p0.x, p0.y);
            A[1] = pack_h2(p1.x, p1.y);
            A[2] = pack_h2(p2.x, p2.y);
            A[3] = pack_h2(p3.x, p3.y);
#pragma unroll
            for (int ni = 0; ni < 4; ni++)
                mma_f16(inj[mi][ni], A, B[s * 4 + ni]);
        }
    }

    // add bias; scatter z1 = relu(inj) into buffer 0 (packed STS.128 per tile)
#pragma unroll
    for (int ni = 0; ni < 4; ni++) {
        float b0v = __ldg(b + 32 * w + 8 * ni + 2 * c);
        float b1v = __ldg(b + 32 * w + 8 * ni + 2 * c + 1);
#pragma unroll
        for (int mi = 0; mi < MI; mi++) {
            inj[mi][ni][0] += b0v;
            inj[mi][ni][1] += b1v;
            inj[mi][ni][2] += b0v;
            inj[mi][ni][3] += b1v;
        }
    }
#pragma unroll
    for (int mi = 0; mi < MI; mi++)
#pragma unroll
        for (int t = 0; t < 2; t++) {   // tile 2w+t holds ni = 2t, 2t+1
            uint4 v;
            v.x = pack_h2_relu(inj[mi][2 * t][0], inj[mi][2 * t][1]);
            v.y = pack_h2_relu(inj[mi][2 * t][2], inj[mi][2 * t][3]);
            v.z = pack_h2_relu(inj[mi][2 * t + 1][0], inj[mi][2 * t + 1][1]);
            v.w = pack_h2_relu(inj[mi][2 * t + 1][2], inj[mi][2 * t + 1][3]);
            uint32_t tile = (uint32_t)(mi * KS + 2 * w + t);
            *reinterpret_cast<uint4*>(sm + tile * 512u + lanerd) = v;
        }

    // ---------------- load Wz B-frags (once; K=128 -> 8 k-steps) ----------------
#pragma unroll
    for (int s = 0; s < KS; s++)
#pragma unroll
        for (int ni = 0; ni < 4; ni++) {
            const float* src = Wz + (32 * w + 8 * ni + g) * HID + 16 * s + 2 * c;
            B[s * 4 + ni][0] = pack_h2(__ldg(src),     __ldg(src + 1));
            B[s * 4 + ni][1] = pack_h2(__ldg(src + 8), __ldg(src + 9));
        }
    __syncthreads();   // z1 scatter visible to all warps

    // ---------------- fixed-point loop: mi-split pipeline, one sync/iter ----------------
    uint32_t rdo = 0;                 // read-buffer byte offset (0 or BUF_BYTES)
    for (int it = 1; it < n_iters; it++) {
#pragma unroll
        for (int mi = 0; mi < MI; mi++) {
            float acc[4][4];
            const char* rdm = sm + rdo + (uint32_t)(mi * KS * 512) + lanerd;

            // 1-deep A prefetch; s=0 folds inj via C operand (no MOV init)
            uint4 a = *reinterpret_cast<const uint4*>(rdm);
#pragma unroll
            for (int s = 0; s < KS; s++) {
                uint32_t A[4] = {a.x, a.y, a.z, a.w};
                if (s + 1 < KS)
                    a = *reinterpret_cast<const uint4*>(rdm + (uint32_t)((s + 1) * 512));
                if (s == 0) {
#pragma unroll
                    for (int ni = 0; ni < 4; ni++)
                        mma_f16_c(acc[ni], A, B[ni], inj[mi][ni]);
                } else {
#pragma unroll
                    for (int ni = 0; ni < 4; ni++)
                        mma_f16(acc[ni], A, B[s * 4 + ni]);
                }
            }

            // epilogue for this mi: 2 packed STS.128 (overlap next mi's MMAs)
            char* wrm = sm + (rdo ^ BUF_BYTES) + (uint32_t)(mi * KS * 512) + lanerd;
#pragma unroll
            for (int t = 0; t < 2; t++) {
                uint4 v;
                v.x = pack_h2_relu(acc[2 * t][0], acc[2 * t][1]);
                v.y = pack_h2_relu(acc[2 * t][2], acc[2 * t][3]);
                v.z = pack_h2_relu(acc[2 * t + 1][0], acc[2 * t + 1][1]);
                v.w = pack_h2_relu(acc[2 * t + 1][2], acc[2 * t + 1][3]);
                *reinterpret_cast<uint4*>(wrm + (uint32_t)((2 * w + t) * 512)) = v;
            }
        }
        __syncthreads();
        rdo ^= BUF_BYTES;
    }

    // ---------------- decoder: out = z @ Wd^T + bd ----------------
    // warp w computes cols [16w, 16w+16): ni 0..1
#pragma unroll
    for (int s = 0; s < KS; s++)
#pragma unroll
        for (int ni = 0; ni < 2; ni++) {
            const float* src = Wd + (16 * w + 8 * ni + g) * HID + 16 * s + 2 * c;
            B[s * 2 + ni][0] = pack_h2(__ldg(src),     __ldg(src + 1));
            B[s * 2 + ni][1] = pack_h2(__ldg(src + 8), __ldg(src + 9));
        }

#pragma unroll
    for (int mi = 0; mi < MI; mi++) {
        float acc2[2][4];
#pragma unroll
        for (int ni = 0; ni < 2; ni++)
#pragma unroll
            for (int r = 0; r < 4; r++) acc2[ni][r] = 0.0f;

        const char* rdm = sm + rdo + (uint32_t)(mi * KS * 512) + lanerd;
#pragma unroll
        for (int s = 0; s < KS; s++) {
            uint4 a = *reinterpret_cast<const uint4*>(rdm + (uint32_t)(s * 512));
            uint32_t A[4] = {a.x, a.y, a.z, a.w};
#pragma unroll
            for (int ni = 0; ni < 2; ni++)
                mma_f16(acc2[ni], A, B[s * 2 + ni]);
        }

        long r0 = rowbase + 16 * mi + g;
        long r1 = r0 + 8;
#pragma unroll
        for (int ni = 0; ni < 2; ni++) {
            int colb = 16 * w + 8 * ni + 2 * c;
            float bd0 = __ldg(bd + colb);
            float bd1 = __ldg(bd + colb + 1);
            if (r0 < rows) {
                float2 v0 = make_float2(acc2[ni][0] + bd0, acc2[ni][1] + bd1);
                *reinterpret_cast<float2*>(out + r0 * OUT_DIM + colb) = v0;
            }
            if (r1 < rows) {
                float2 v1 = make_float2(acc2[ni][2] + bd0, acc2[ni][3] + bd1);
                *reinterpret_cast<float2*>(out + r1 * OUT_DIM + colb) = v1;
            }
        }
    }
}

// ==================== launch ====================
extern "C" void kernel_launch(void* const* d_in, const int* in_sizes, int n_in,
                              void* d_out, int out_size) {
    const float* x   = (const float*)d_in[0];
    const float* Wz  = (const float*)d_in[1];
    const float* Ux  = (const float*)d_in[2];
    const float* b   = (const float*)d_in[3];
    const float* Wd  = (const float*)d_in[4];
    const float* bd  = (const float*)d_in[5];
    const int*   nit = (const int*)d_in[6];
    float* out = (float*)d_out;

    int rows = in_sizes[0] / IN_DIM;
    int grid = (rows + ROWS_PER_CTA - 1) / ROWS_PER_CTA;

    cudaFuncSetAttribute(deq_mma_kernel,
                         cudaFuncAttributeMaxDynamicSharedMemorySize, SMEM_TOTAL);

    deq_mma_kernel<<<grid, THREADS, SMEM_TOTAL>>>(x, Wz, Ux, b, Wd, bd, nit, out, rows);
}